// round 1
// baseline (speedup 1.0000x reference)
#include <cuda_runtime.h>
#include <cuda_bf16.h>
#include <cstdint>

#define ND 128
#define NQ 128
#define LD 128
#define LQ 32
#define EDIM 128

// bf16 scratch (device globals: no allocation allowed in kernel_launch)
__device__ __nv_bfloat16 g_doc[ND * LD * EDIM];      // [d][t][e]
__device__ __nv_bfloat16 g_qT[NQ * LQ * EDIM];       // [q][l][e]

// ---------------------------------------------------------------------------
// Conversion kernels
// ---------------------------------------------------------------------------
__global__ void conv_doc_kernel(const float* __restrict__ in) {
    int i = blockIdx.x * blockDim.x + threadIdx.x;   // 2048 blocks * 1024 = 2M
    g_doc[i] = __float2bfloat16(in[i]);
}

__global__ void conv_q_kernel(const float* __restrict__ in) {
    // in: [q][e][l]  (q*4096 + e*32 + l)  ->  g_qT: [q][l][e]
    int idx = blockIdx.x * blockDim.x + threadIdx.x; // 512 blocks * 1024 = 512K
    int q = idx >> 12;
    int rem = idx & 4095;
    int e = rem >> 5;
    int l = rem & 31;
    g_qT[q * (LQ * EDIM) + l * EDIM + e] = __float2bfloat16(in[idx]);
}

// ---------------------------------------------------------------------------
// mma.sync m16n8k16 bf16 -> f32
// A frag: a0=(g,2t) a1=(g+8,2t) a2=(g,2t+8) a3=(g+8,2t+8)   (each reg = 2 consecutive k)
// B frag: b0=(k=2t,n=g) b1=(k=2t+8,n=g)                      (each reg = 2 consecutive k)
// C frag: c0=(g,2t) c1=(g,2t+1) c2=(g+8,2t) c3=(g+8,2t+1)
// ---------------------------------------------------------------------------
__device__ __forceinline__ void mma16816(float* c, const uint32_t* a, const uint32_t* b) {
    asm volatile(
        "mma.sync.aligned.m16n8k16.row.col.f32.bf16.bf16.f32 "
        "{%0,%1,%2,%3}, {%4,%5,%6,%7}, {%8,%9}, {%0,%1,%2,%3};\n"
        : "+f"(c[0]), "+f"(c[1]), "+f"(c[2]), "+f"(c[3])
        : "r"(a[0]), "r"(a[1]), "r"(a[2]), "r"(a[3]),
          "r"(b[0]), "r"(b[1]));
}

// padded smem row stride (bf16 elems). 136*2 = 272 B = 17 * 16 B -> uint4-aligned rows,
// and (row*68) mod 32 = row*4 -> conflict-free 32-bit fragment loads.
#define LDA 136

__global__ __launch_bounds__(128) void maxsim_kernel(float* __restrict__ out) {
    const int d = blockIdx.x;
    const int q = blockIdx.y;

    __shared__ alignas(16) __nv_bfloat16 As[LD * LDA];   // doc tile  [t][e]
    __shared__ alignas(16) __nv_bfloat16 Bs[LQ * LDA];   // query tile [l][e]
    __shared__ float colmax[4][LQ];

    const int tid = threadIdx.x;

    // --- load doc tile (128x128 bf16 = 2048 uint4) ---
    {
        const uint4* src = reinterpret_cast<const uint4*>(g_doc + d * (LD * EDIM));
        uint4* dst = reinterpret_cast<uint4*>(As);
        #pragma unroll
        for (int i = 0; i < 16; i++) {
            int idx = tid + i * 128;         // 0..2047
            int row = idx >> 4;              // 16 uint4 per row of 128 bf16
            int col = idx & 15;
            dst[row * 17 + col] = src[idx];
        }
    }
    // --- load query tile (32x128 bf16 = 512 uint4) ---
    {
        const uint4* src = reinterpret_cast<const uint4*>(g_qT + q * (LQ * EDIM));
        uint4* dst = reinterpret_cast<uint4*>(Bs);
        #pragma unroll
        for (int i = 0; i < 4; i++) {
            int idx = tid + i * 128;         // 0..511
            int row = idx >> 4;
            int col = idx & 15;
            dst[row * 17 + col] = src[idx];
        }
    }
    __syncthreads();

    const int warp = tid >> 5;
    const int lane = tid & 31;
    const int g = lane >> 2;     // group id 0..7
    const int t4 = lane & 3;     // thread-in-group 0..3

    // warp w covers doc rows [w*32, w*32+32), all 32 query cols
    float acc[2][4][4];
    #pragma unroll
    for (int mt = 0; mt < 2; mt++)
        #pragma unroll
        for (int nt = 0; nt < 4; nt++)
            #pragma unroll
            for (int i = 0; i < 4; i++)
                acc[mt][nt][i] = 0.0f;

    const int mbase = warp * 32;

    #pragma unroll
    for (int k0 = 0; k0 < EDIM; k0 += 16) {
        uint32_t a[2][4];
        #pragma unroll
        for (int mt = 0; mt < 2; mt++) {
            const int r0 = mbase + mt * 16 + g;
            const __nv_bfloat16* p0 = &As[r0 * LDA + k0 + t4 * 2];
            const __nv_bfloat16* p1 = &As[(r0 + 8) * LDA + k0 + t4 * 2];
            a[mt][0] = *reinterpret_cast<const uint32_t*>(p0);
            a[mt][1] = *reinterpret_cast<const uint32_t*>(p1);
            a[mt][2] = *reinterpret_cast<const uint32_t*>(p0 + 8);
            a[mt][3] = *reinterpret_cast<const uint32_t*>(p1 + 8);
        }
        uint32_t b[4][2];
        #pragma unroll
        for (int nt = 0; nt < 4; nt++) {
            const __nv_bfloat16* pb = &Bs[(nt * 8 + g) * LDA + k0 + t4 * 2];
            b[nt][0] = *reinterpret_cast<const uint32_t*>(pb);
            b[nt][1] = *reinterpret_cast<const uint32_t*>(pb + 8);
        }
        #pragma unroll
        for (int mt = 0; mt < 2; mt++)
            #pragma unroll
            for (int nt = 0; nt < 4; nt++)
                mma16816(acc[mt][nt], a[mt], b[nt]);
    }

    // --- epilogue: max over this warp's 32 doc rows, per query column ---
    #pragma unroll
    for (int nt = 0; nt < 4; nt++) {
        // col = nt*8 + 2*t4 (m0) and +1 (m1); rows g, g+8 within both m-tiles
        float m0 = fmaxf(fmaxf(acc[0][nt][0], acc[0][nt][2]),
                         fmaxf(acc[1][nt][0], acc[1][nt][2]));
        float m1 = fmaxf(fmaxf(acc[0][nt][1], acc[0][nt][3]),
                         fmaxf(acc[1][nt][1], acc[1][nt][3]));
        #pragma unroll
        for (int off = 4; off < 32; off <<= 1) {
            m0 = fmaxf(m0, __shfl_xor_sync(0xffffffffu, m0, off));
            m1 = fmaxf(m1, __shfl_xor_sync(0xffffffffu, m1, off));
        }
        if (lane < 4) {  // lane == t4
            colmax[warp][nt * 8 + 2 * t4]     = m0;
            colmax[warp][nt * 8 + 2 * t4 + 1] = m1;
        }
    }
    __syncthreads();

    // --- cross-warp max + sum over the 32 query columns ---
    if (warp == 0) {
        float v = fmaxf(fmaxf(colmax[0][lane], colmax[1][lane]),
                        fmaxf(colmax[2][lane], colmax[3][lane]));
        #pragma unroll
        for (int off = 16; off; off >>= 1)
            v += __shfl_xor_sync(0xffffffffu, v, off);
        if (lane == 0)
            out[q * ND + d] = v;
    }
}

// ---------------------------------------------------------------------------
extern "C" void kernel_launch(void* const* d_in, const int* in_sizes, int n_in,
                              void* d_out, int out_size) {
    const float* doc   = (const float*)d_in[0];   // [128,128,128]
    const float* query = (const float*)d_in[1];   // [128,128,32]
    float* out = (float*)d_out;                   // [128,128]

    conv_doc_kernel<<<2048, 1024>>>(doc);
    conv_q_kernel<<<512, 1024>>>(query);

    dim3 grid(ND, NQ);
    maxsim_kernel<<<grid, 128>>>(out);
}

// round 3
// speedup vs baseline: 1.5002x; 1.5002x over previous
#include <cuda_runtime.h>
#include <cuda_bf16.h>
#include <cstdint>

#define ND 128
#define NQ 128
#define LD 128
#define LQ 32
#define EDIM 128

// bf16 staging (device globals: no allocation allowed)
__device__ __nv_bfloat16 g_doc[ND * LD * EDIM];      // [d][t][e]
__device__ __nv_bfloat16 g_qT[NQ * LQ * EDIM];       // [q][l][e]

// ---------------------------------------------------------------------------
// Conversion kernels (vectorized)
// ---------------------------------------------------------------------------
__global__ void conv_doc_kernel(const float* __restrict__ in) {
    int i = blockIdx.x * blockDim.x + threadIdx.x;        // 524288 threads, float4 each
    float4 v = reinterpret_cast<const float4*>(in)[i];
    __nv_bfloat162 lo = __floats2bfloat162_rn(v.x, v.y);
    __nv_bfloat162 hi = __floats2bfloat162_rn(v.z, v.w);
    uint2 o;
    o.x = *reinterpret_cast<uint32_t*>(&lo);
    o.y = *reinterpret_cast<uint32_t*>(&hi);
    reinterpret_cast<uint2*>(g_doc)[i] = o;
}

__global__ void conv_q_kernel(const float* __restrict__ in) {
    // in[q][e][l] (e:128, l:32)  ->  g_qT[q][l][e]
    __shared__ float s[128 * 33];
    int q = blockIdx.x;
    const float* src = in + q * 4096;
    int tid = threadIdx.x;  // 256
    #pragma unroll
    for (int i = 0; i < 16; i++) {
        int idx = tid + i * 256;
        int e = idx >> 5, l = idx & 31;
        s[e * 33 + l] = src[idx];
    }
    __syncthreads();
    __nv_bfloat16* dst = g_qT + q * 4096;
    #pragma unroll
    for (int i = 0; i < 16; i++) {
        int idx = tid + i * 256;
        int l = idx >> 7, e = idx & 127;
        dst[idx] = __float2bfloat16(s[e * 33 + l]);
    }
}

// ---------------------------------------------------------------------------
// mma.sync m16n8k16 bf16 -> f32   (fragment layout verified in Round 1)
// ---------------------------------------------------------------------------
__device__ __forceinline__ void mma16816(float* c, const uint32_t* a, const uint32_t* b) {
    asm volatile(
        "mma.sync.aligned.m16n8k16.row.col.f32.bf16.bf16.f32 "
        "{%0,%1,%2,%3}, {%4,%5,%6,%7}, {%8,%9}, {%0,%1,%2,%3};\n"
        : "+f"(c[0]), "+f"(c[1]), "+f"(c[2]), "+f"(c[3])
        : "r"(a[0]), "r"(a[1]), "r"(a[2]), "r"(a[3]),
          "r"(b[0]), "r"(b[1]));
}

// padded smem row stride in bf16 elems: 136*2 = 272 B (16B-aligned rows,
// conflict-free 32-bit fragment loads — verified in Round 1)
#define LDA 136
#define AS_BYTES (128 * LDA * 2)     // 34816
#define BS_BYTES (128 * LDA * 2)     // 34816
#define CM_BYTES (4 * 128 * 4)       // 2048
#define SMEM_TOTAL (AS_BYTES + BS_BYTES + CM_BYTES)   // 71680

// CTA: 256 threads = 8 warps in 4(m) x 2(n).
// M = 128 doc tokens (one doc), N = 128 ql rows (4 queries x 32 sentence slots).
__global__ void __launch_bounds__(256) maxsim_kernel(float* __restrict__ out) {
    extern __shared__ char smem[];
    __nv_bfloat16* As = reinterpret_cast<__nv_bfloat16*>(smem);                 // [t][e]
    __nv_bfloat16* Bs = reinterpret_cast<__nv_bfloat16*>(smem + AS_BYTES);      // [ql][e]
    float* colmax = reinterpret_cast<float*>(smem + AS_BYTES + BS_BYTES);       // [4][128]

    const int d = blockIdx.x;
    const int qg = blockIdx.y;
    const int tid = threadIdx.x;

    // ---- load doc tile [128 t x 128 e] (2048 uint4) ----
    {
        const uint4* src = reinterpret_cast<const uint4*>(g_doc + d * (LD * EDIM));
        uint4* dst = reinterpret_cast<uint4*>(As);
        #pragma unroll
        for (int i = 0; i < 8; i++) {
            int idx = tid + i * 256;
            int row = idx >> 4, col = idx & 15;
            dst[row * 17 + col] = src[idx];
        }
    }
    // ---- load query-group tile [128 ql x 128 e] (2048 uint4) ----
    {
        const uint4* src = reinterpret_cast<const uint4*>(g_qT + qg * 4 * (LQ * EDIM));
        uint4* dst = reinterpret_cast<uint4*>(Bs);
        #pragma unroll
        for (int i = 0; i < 8; i++) {
            int idx = tid + i * 256;
            int row = idx >> 4, col = idx & 15;
            dst[row * 17 + col] = src[idx];
        }
    }
    __syncthreads();

    const int warp = tid >> 5;
    const int lane = tid & 31;
    const int wm = warp >> 1;     // 0..3  (m: doc tokens)
    const int wn = warp & 1;      // 0..1  (n: ql columns)
    const int g = lane >> 2;      // 0..7
    const int t4 = lane & 3;      // 0..3

    const int mbase = wm * 32;
    const int nbase = wn * 64;

    float acc[2][8][4];
    #pragma unroll
    for (int mt = 0; mt < 2; mt++)
        #pragma unroll
        for (int nt = 0; nt < 8; nt++)
            #pragma unroll
            for (int i = 0; i < 4; i++)
                acc[mt][nt][i] = 0.0f;

    #pragma unroll
    for (int k0 = 0; k0 < EDIM; k0 += 16) {
        uint32_t a[2][4];
        #pragma unroll
        for (int mt = 0; mt < 2; mt++) {
            const int r0 = mbase + mt * 16 + g;
            const __nv_bfloat16* p0 = &As[r0 * LDA + k0 + t4 * 2];
            const __nv_bfloat16* p1 = &As[(r0 + 8) * LDA + k0 + t4 * 2];
            a[mt][0] = *reinterpret_cast<const uint32_t*>(p0);
            a[mt][1] = *reinterpret_cast<const uint32_t*>(p1);
            a[mt][2] = *reinterpret_cast<const uint32_t*>(p0 + 8);
            a[mt][3] = *reinterpret_cast<const uint32_t*>(p1 + 8);
        }
        uint32_t b[8][2];
        #pragma unroll
        for (int nt = 0; nt < 8; nt++) {
            const __nv_bfloat16* pb = &Bs[(nbase + nt * 8 + g) * LDA + k0 + t4 * 2];
            b[nt][0] = *reinterpret_cast<const uint32_t*>(pb);
            b[nt][1] = *reinterpret_cast<const uint32_t*>(pb + 8);
        }
        #pragma unroll
        for (int mt = 0; mt < 2; mt++)
            #pragma unroll
            for (int nt = 0; nt < 8; nt++)
                mma16816(acc[mt][nt], a[mt], b[nt]);
    }

    // ---- per-warp max over its 32 doc-token rows, per ql column ----
    #pragma unroll
    for (int nt = 0; nt < 8; nt++) {
        // columns nbase + nt*8 + 2*t4 (+1); rows covered by this thread: g, g+8 in 2 m-tiles
        float m0 = fmaxf(fmaxf(acc[0][nt][0], acc[0][nt][2]),
                         fmaxf(acc[1][nt][0], acc[1][nt][2]));
        float m1 = fmaxf(fmaxf(acc[0][nt][1], acc[0][nt][3]),
                         fmaxf(acc[1][nt][1], acc[1][nt][3]));
        #pragma unroll
        for (int off = 4; off < 32; off <<= 1) {
            m0 = fmaxf(m0, __shfl_xor_sync(0xffffffffu, m0, off));
            m1 = fmaxf(m1, __shfl_xor_sync(0xffffffffu, m1, off));
        }
        if (lane < 4) {   // lane == t4
            colmax[wm * 128 + nbase + nt * 8 + 2 * t4]     = m0;
            colmax[wm * 128 + nbase + nt * 8 + 2 * t4 + 1] = m1;
        }
    }
    __syncthreads();

    // ---- cross-warp max over t (4 m-warps), then sum over l per query ----
    if (tid < 128) {
        const int col = tid;   // ql index within group
        float v = fmaxf(fmaxf(colmax[0 * 128 + col], colmax[1 * 128 + col]),
                        fmaxf(colmax[2 * 128 + col], colmax[3 * 128 + col]));
        #pragma unroll
        for (int off = 16; off; off >>= 1)
            v += __shfl_xor_sync(0xffffffffu, v, off);
        if ((col & 31) == 0)
            out[(qg * 4 + (col >> 5)) * ND + d] = v;
    }
}

// ---------------------------------------------------------------------------
extern "C" void kernel_launch(void* const* d_in, const int* in_sizes, int n_in,
                              void* d_out, int out_size) {
    const float* doc   = (const float*)d_in[0];   // [128,128,128]
    const float* query = (const float*)d_in[1];   // [128,128,32]
    float* out = (float*)d_out;                   // [128,128]

    static bool attr_set = false;
    if (!attr_set) {
        cudaFuncSetAttribute(maxsim_kernel, cudaFuncAttributeMaxDynamicSharedMemorySize,
                             SMEM_TOTAL);
        attr_set = true;
    }

    conv_doc_kernel<<<2048, 256>>>(doc);
    conv_q_kernel<<<128, 256>>>(query);

    dim3 grid(ND, LQ);   // 128 docs x 32 query groups
    maxsim_kernel<<<grid, 256, SMEM_TOTAL>>>(out);
}

// round 4
// speedup vs baseline: 1.6111x; 1.0739x over previous
#include <cuda_runtime.h>
#include <cuda_bf16.h>
#include <cstdint>

#define ND 128
#define NQ 128
#define LD 128
#define LQ 32
#define EDIM 128

// bf16 staging (device globals: no allocation allowed)
__device__ __nv_bfloat16 g_doc[ND * LD * EDIM];      // [d][t][e]
__device__ __nv_bfloat16 g_qT[NQ * LQ * EDIM];       // [q][l][e]

// ---------------------------------------------------------------------------
// Conversion kernels
// ---------------------------------------------------------------------------
__global__ void conv_doc_kernel(const float* __restrict__ in) {
    int base = blockIdx.x * blockDim.x + threadIdx.x;   // 1024*256 threads, 2 float4 each
    #pragma unroll
    for (int it = 0; it < 2; it++) {
        int i = base + it * 262144;
        float4 v = reinterpret_cast<const float4*>(in)[i];
        __nv_bfloat162 lo = __floats2bfloat162_rn(v.x, v.y);
        __nv_bfloat162 hi = __floats2bfloat162_rn(v.z, v.w);
        uint2 o;
        o.x = *reinterpret_cast<uint32_t*>(&lo);
        o.y = *reinterpret_cast<uint32_t*>(&hi);
        reinterpret_cast<uint2*>(g_doc)[i] = o;
    }
}

__global__ void conv_q_kernel(const float* __restrict__ in) {
    // in[q][e][l] (e:128, l:32)  ->  g_qT[q][l][e]
    __shared__ float s[128 * 33];
    int q = blockIdx.x;
    const float* src = in + q * 4096;
    int tid = threadIdx.x;  // 256
    #pragma unroll
    for (int i = 0; i < 16; i++) {
        int idx = tid + i * 256;
        int e = idx >> 5, l = idx & 31;
        s[e * 33 + l] = src[idx];
    }
    __syncthreads();
    __nv_bfloat16* dst = g_qT + q * 4096;
    #pragma unroll
    for (int i = 0; i < 16; i++) {
        int idx = tid + i * 256;
        int l = idx >> 7, e = idx & 127;
        dst[idx] = __float2bfloat16(s[e * 33 + l]);
    }
}

// ---------------------------------------------------------------------------
// MMA / LDSM primitives
// ---------------------------------------------------------------------------
__device__ __forceinline__ void mma16816(float* c, const uint32_t* a, const uint32_t* b) {
    asm volatile(
        "mma.sync.aligned.m16n8k16.row.col.f32.bf16.bf16.f32 "
        "{%0,%1,%2,%3}, {%4,%5,%6,%7}, {%8,%9}, {%0,%1,%2,%3};\n"
        : "+f"(c[0]), "+f"(c[1]), "+f"(c[2]), "+f"(c[3])
        : "r"(a[0]), "r"(a[1]), "r"(a[2]), "r"(a[3]),
          "r"(b[0]), "r"(b[1]));
}

#define LDSM_X4(r0, r1, r2, r3, addr) \
    asm volatile("ldmatrix.sync.aligned.m8n8.x4.shared.b16 {%0,%1,%2,%3}, [%4];" \
                 : "=r"(r0), "=r"(r1), "=r"(r2), "=r"(r3) : "r"(addr))

__device__ __forceinline__ uint32_t smem_u32(const void* p) {
    uint32_t a;
    asm("{ .reg .u64 t; cvta.to.shared.u64 t, %1; cvt.u32.u64 %0, t; }" : "=r"(a) : "l"(p));
    return a;
}

// padded smem row: 136 bf16 = 272 B. Rows r, r+1 start 68 words apart ->
// LDSM 8-row phases hit banks {4r..4r+3}: all 32 banks, conflict-free.
#define LDA 136
#define ROWB 272
#define TILE_BYTES (128 * ROWB)                  // 34816
#define AS_OFF(dd) ((dd) * TILE_BYTES)
#define BS_OFF (2 * TILE_BYTES)
#define CM_OFF (3 * TILE_BYTES)                  // colmax [2][128] floats
#define SMEM_TOTAL (3 * TILE_BYTES + 1024)       // 105472

// CTA: 128 threads = 4 warps, 2(m) x 2(n); warp tile 64x64.
// M = 128 doc tokens, N = 128 ql (4 queries). 2 docs per CTA, sequential passes.
__global__ void __launch_bounds__(128) maxsim_kernel(float* __restrict__ out) {
    extern __shared__ char smem[];
    float* colmax = reinterpret_cast<float*>(smem + CM_OFF);   // [2][128]

    const int dbase = blockIdx.x * 2;
    const int qg = blockIdx.y;
    const int tid = threadIdx.x;
    const int warp = tid >> 5;
    const int lane = tid & 31;
    const int wm = warp >> 1;     // 0..1
    const int wn = warp & 1;      // 0..1
    const int g = lane >> 2;
    const int t4 = lane & 3;
    const int matid = lane >> 3;  // 0..3
    const int mrow = lane & 7;

    // ---- load tiles: 2 doc tiles + 1 query tile (each 2048 uint4) ----
    {
        const uint4* srcq = reinterpret_cast<const uint4*>(g_qT + qg * 4 * LQ * EDIM);
        const uint4* srcd0 = reinterpret_cast<const uint4*>(g_doc + dbase * LD * EDIM);
        const uint4* srcd1 = reinterpret_cast<const uint4*>(g_doc + (dbase + 1) * LD * EDIM);
        uint4* dA0 = reinterpret_cast<uint4*>(smem + AS_OFF(0));
        uint4* dA1 = reinterpret_cast<uint4*>(smem + AS_OFF(1));
        uint4* dB  = reinterpret_cast<uint4*>(smem + BS_OFF);
        #pragma unroll
        for (int i = 0; i < 16; i++) {
            int idx = tid + i * 128;
            int row = idx >> 4, col = idx & 15;
            int soff = row * 17 + col;
            dA0[soff] = srcd0[idx];
            dA1[soff] = srcd1[idx];
            dB[soff]  = srcq[idx];
        }
    }
    __syncthreads();

    const uint32_t sbase = smem_u32(smem);
    // Per-lane LDSM base addresses (k0 added in loop).
    // A (rows = doc tokens): matid bit0 -> +8 rows, bit1 -> +8 k elems (16 B)
    uint32_t a_addr[2];
    #pragma unroll
    for (int mt2 = 0; mt2 < 2; mt2++) { /* placeholder, real init below */ a_addr[mt2] = 0; }
    uint32_t arow_off[4];
    #pragma unroll
    for (int mt = 0; mt < 4; mt++)
        arow_off[mt] = (uint32_t)((wm * 64 + mt * 16 + (matid & 1) * 8 + mrow) * ROWB
                                  + (matid >> 1) * 16);
    // B (rows = ql): matid bit1 -> +8 rows (n), bit0 -> +8 k elems
    uint32_t brow_off[4];
    #pragma unroll
    for (int np = 0; np < 4; np++)
        brow_off[np] = (uint32_t)(BS_OFF + (wn * 64 + np * 16 + (matid >> 1) * 8 + mrow) * ROWB
                                  + (matid & 1) * 16);

    #pragma unroll
    for (int dd = 0; dd < 2; dd++) {
        const uint32_t sA = sbase + AS_OFF(dd);

        float acc[4][8][4];
        #pragma unroll
        for (int mt = 0; mt < 4; mt++)
            #pragma unroll
            for (int nt = 0; nt < 8; nt++)
                #pragma unroll
                for (int i = 0; i < 4; i++)
                    acc[mt][nt][i] = 0.0f;

        #pragma unroll
        for (int k0 = 0; k0 < EDIM; k0 += 16) {
            uint32_t a[4][4], b[8][2];
            #pragma unroll
            for (int mt = 0; mt < 4; mt++)
                LDSM_X4(a[mt][0], a[mt][1], a[mt][2], a[mt][3], sA + arow_off[mt] + k0 * 2);
            #pragma unroll
            for (int np = 0; np < 4; np++) {
                uint32_t t0, t1, t2, t3;
                LDSM_X4(t0, t1, t2, t3, sbase + brow_off[np] + k0 * 2);
                b[2 * np][0] = t0; b[2 * np][1] = t1;
                b[2 * np + 1][0] = t2; b[2 * np + 1][1] = t3;
            }
            #pragma unroll
            for (int mt = 0; mt < 4; mt++)
                #pragma unroll
                for (int nt = 0; nt < 8; nt++)
                    mma16816(acc[mt][nt], a[mt], b[nt]);
        }

        // ---- warp-level max over its 64 doc-token rows, per ql column ----
        #pragma unroll
        for (int nt = 0; nt < 8; nt++) {
            float m0 = -3.4e38f, m1 = -3.4e38f;
            #pragma unroll
            for (int mt = 0; mt < 4; mt++) {
                m0 = fmaxf(m0, fmaxf(acc[mt][nt][0], acc[mt][nt][2]));
                m1 = fmaxf(m1, fmaxf(acc[mt][nt][1], acc[mt][nt][3]));
            }
            #pragma unroll
            for (int off = 4; off < 32; off <<= 1) {
                m0 = fmaxf(m0, __shfl_xor_sync(0xffffffffu, m0, off));
                m1 = fmaxf(m1, __shfl_xor_sync(0xffffffffu, m1, off));
            }
            if (lane < 4) {   // lane == t4
                colmax[wm * 128 + wn * 64 + nt * 8 + 2 * t4]     = m0;
                colmax[wm * 128 + wn * 64 + nt * 8 + 2 * t4 + 1] = m1;
            }
        }
        __syncthreads();

        // ---- cross-warp max over t, then sum over l per query ----
        {
            float v = fmaxf(colmax[tid], colmax[128 + tid]);
            #pragma unroll
            for (int off = 16; off; off >>= 1)
                v += __shfl_xor_sync(0xffffffffu, v, off);
            if (lane == 0)
                out[(qg * 4 + warp) * ND + dbase + dd] = v;
        }
        __syncthreads();   // protect colmax before next pass
    }
}

// ---------------------------------------------------------------------------
extern "C" void kernel_launch(void* const* d_in, const int* in_sizes, int n_in,
                              void* d_out, int out_size) {
    const float* doc   = (const float*)d_in[0];   // [128,128,128]
    const float* query = (const float*)d_in[1];   // [128,128,32]
    float* out = (float*)d_out;                   // [128,128]

    static bool attr_set = false;
    if (!attr_set) {
        cudaFuncSetAttribute(maxsim_kernel, cudaFuncAttributeMaxDynamicSharedMemorySize,
                             SMEM_TOTAL);
        attr_set = true;
    }

    conv_doc_kernel<<<1024, 256>>>(doc);
    conv_q_kernel<<<128, 256>>>(query);

    dim3 grid(ND / 2, LQ);   // 64 doc-pairs x 32 query groups
    maxsim_kernel<<<grid, 128, SMEM_TOTAL>>>(out);
}

// round 5
// speedup vs baseline: 1.7757x; 1.1021x over previous
#include <cuda_runtime.h>
#include <cuda_fp16.h>
#include <cstdint>

#define ND 128
#define NQ 128
#define LD 128
#define LQ 32
#define EDIM 128

// f16 staging (device globals: no allocation allowed)
__device__ __half g_doc[ND * LD * EDIM];      // [d][t][e]
__device__ __half g_qT[NQ * LQ * EDIM];       // [q][l][e]

// ---------------------------------------------------------------------------
// Merged conversion kernel: blocks [0,1024) convert doc, [1024,1152) convert q
// ---------------------------------------------------------------------------
__global__ void conv_all_kernel(const float* __restrict__ doc, const float* __restrict__ q) {
    __shared__ float s[128 * 33];
    if (blockIdx.x < 1024) {
        int base = blockIdx.x * blockDim.x + threadIdx.x;    // 262144 threads
        #pragma unroll
        for (int it = 0; it < 2; it++) {
            int i = base + it * 262144;
            float4 v = reinterpret_cast<const float4*>(doc)[i];
            __half2 lo = __floats2half2_rn(v.x, v.y);
            __half2 hi = __floats2half2_rn(v.z, v.w);
            uint2 o;
            o.x = *reinterpret_cast<uint32_t*>(&lo);
            o.y = *reinterpret_cast<uint32_t*>(&hi);
            reinterpret_cast<uint2*>(g_doc)[i] = o;
        }
    } else {
        // in[q][e][l] (e:128, l:32)  ->  g_qT[q][l][e]
        int qq = blockIdx.x - 1024;
        const float* src = q + qq * 4096;
        int tid = threadIdx.x;  // 256
        #pragma unroll
        for (int i = 0; i < 16; i++) {
            int idx = tid + i * 256;
            int e = idx >> 5, l = idx & 31;
            s[e * 33 + l] = src[idx];
        }
        __syncthreads();
        __half* dst = g_qT + qq * 4096;
        #pragma unroll
        for (int i = 0; i < 16; i++) {
            int idx = tid + i * 256;
            int l = idx >> 7, e = idx & 127;
            dst[idx] = __float2half_rn(s[e * 33 + l]);
        }
    }
}

// ---------------------------------------------------------------------------
// Primitives
// ---------------------------------------------------------------------------
__device__ __forceinline__ void mma16816_f16(uint32_t* c, const uint32_t* a, const uint32_t* b) {
    asm volatile(
        "mma.sync.aligned.m16n8k16.row.col.f16.f16.f16.f16 "
        "{%0,%1}, {%2,%3,%4,%5}, {%6,%7}, {%0,%1};\n"
        : "+r"(c[0]), "+r"(c[1])
        : "r"(a[0]), "r"(a[1]), "r"(a[2]), "r"(a[3]),
          "r"(b[0]), "r"(b[1]));
}

#define LDSM_X4(r0, r1, r2, r3, addr) \
    asm volatile("ldmatrix.sync.aligned.m8n8.x4.shared.b16 {%0,%1,%2,%3}, [%4];" \
                 : "=r"(r0), "=r"(r1), "=r"(r2), "=r"(r3) : "r"(addr))

__device__ __forceinline__ uint32_t smem_u32(const void* p) {
    uint32_t a;
    asm("{ .reg .u64 t; cvta.to.shared.u64 t, %1; cvt.u32.u64 %0, t; }" : "=r"(a) : "l"(p));
    return a;
}

#define CP16(saddr, gptr) \
    asm volatile("cp.async.cg.shared.global [%0], [%1], 16;" :: "r"(saddr), "l"(gptr))
#define CP_COMMIT() asm volatile("cp.async.commit_group;")
#define CP_WAIT(n)  asm volatile("cp.async.wait_group %0;" :: "n"(n))

// padded smem row: 136 f16 = 272 B (conflict-free LDSM, verified R4)
#define ROWB 272
#define TILE_BYTES (128 * ROWB)                  // 34816
#define A_OFF(buf) ((buf) * TILE_BYTES)
#define B_OFF (2 * TILE_BYTES)
#define CM_OFF (3 * TILE_BYTES)
#define SMEM_TOTAL (3 * TILE_BYTES + 1024)       // 105472

// CTA: 128 threads = 4 warps (2m x 2n), warp tile 64x64, f16 accumulators.
// 2 docs per CTA, cp.async double-buffered.
__global__ void __launch_bounds__(128) maxsim_kernel(float* __restrict__ out) {
    extern __shared__ char smem[];
    float* colmax = reinterpret_cast<float*>(smem + CM_OFF);   // [2][128]

    const int dbase = blockIdx.x * 2;
    const int qg = blockIdx.y;
    const int tid = threadIdx.x;
    const int warp = tid >> 5;
    const int lane = tid & 31;
    const int wm = warp >> 1;
    const int wn = warp & 1;
    const int t4 = lane & 3;
    const int matid = lane >> 3;
    const int mrow = lane & 7;

    const uint32_t sbase = smem_u32(smem);

    // ---- async tile loads: group A = (q, doc0), group B = doc1 ----
    {
        const uint4* srcq  = reinterpret_cast<const uint4*>(g_qT + qg * 4 * LQ * EDIM);
        const uint4* srcd0 = reinterpret_cast<const uint4*>(g_doc + dbase * LD * EDIM);
        const uint4* srcd1 = reinterpret_cast<const uint4*>(g_doc + (dbase + 1) * LD * EDIM);
        #pragma unroll
        for (int i = 0; i < 16; i++) {
            int idx = tid + i * 128;
            int row = idx >> 4, col = idx & 15;
            uint32_t soff = (uint32_t)(row * 17 + col) * 16;
            CP16(sbase + B_OFF + soff, srcq + idx);
            CP16(sbase + A_OFF(0) + soff, srcd0 + idx);
        }
        CP_COMMIT();
        #pragma unroll
        for (int i = 0; i < 16; i++) {
            int idx = tid + i * 128;
            int row = idx >> 4, col = idx & 15;
            uint32_t soff = (uint32_t)(row * 17 + col) * 16;
            CP16(sbase + A_OFF(1) + soff, srcd1 + idx);
        }
        CP_COMMIT();
    }

    // LDSM per-lane offsets (verified R4 mapping)
    uint32_t arow_off[4];
    #pragma unroll
    for (int mt = 0; mt < 4; mt++)
        arow_off[mt] = (uint32_t)((wm * 64 + mt * 16 + (matid & 1) * 8 + mrow) * ROWB
                                  + (matid >> 1) * 16);
    uint32_t brow_off[4];
    #pragma unroll
    for (int np = 0; np < 4; np++)
        brow_off[np] = (uint32_t)(B_OFF + (wn * 64 + np * 16 + (matid >> 1) * 8 + mrow) * ROWB
                                  + (matid & 1) * 16);

    CP_WAIT(1);            // q + doc0 resident
    __syncthreads();

    #pragma unroll
    for (int dd = 0; dd < 2; dd++) {
        const uint32_t sA = sbase + A_OFF(dd);

        uint32_t acc[4][8][2];
        #pragma unroll
        for (int mt = 0; mt < 4; mt++)
            #pragma unroll
            for (int nt = 0; nt < 8; nt++) {
                acc[mt][nt][0] = 0u;
                acc[mt][nt][1] = 0u;
            }

        #pragma unroll
        for (int k0 = 0; k0 < EDIM; k0 += 16) {
            uint32_t a[4][4], b[8][2];
            #pragma unroll
            for (int mt = 0; mt < 4; mt++)
                LDSM_X4(a[mt][0], a[mt][1], a[mt][2], a[mt][3], sA + arow_off[mt] + k0 * 2);
            #pragma unroll
            for (int np = 0; np < 4; np++) {
                uint32_t t0, t1, t2, t3;
                LDSM_X4(t0, t1, t2, t3, sbase + brow_off[np] + k0 * 2);
                b[2 * np][0] = t0; b[2 * np][1] = t1;
                b[2 * np + 1][0] = t2; b[2 * np + 1][1] = t3;
            }
            #pragma unroll
            for (int mt = 0; mt < 4; mt++)
                #pragma unroll
                for (int nt = 0; nt < 8; nt++)
                    mma16816_f16(acc[mt][nt], a[mt], b[nt]);
        }

        // ---- warp max over its 64 doc-token rows (packed f16x2 per col pair) ----
        #pragma unroll
        for (int nt = 0; nt < 8; nt++) {
            __half2 hm = __hmax2(*reinterpret_cast<__half2*>(&acc[0][nt][0]),
                                 *reinterpret_cast<__half2*>(&acc[0][nt][1]));
            #pragma unroll
            for (int mt = 1; mt < 4; mt++) {
                hm = __hmax2(hm, *reinterpret_cast<__half2*>(&acc[mt][nt][0]));
                hm = __hmax2(hm, *reinterpret_cast<__half2*>(&acc[mt][nt][1]));
            }
            #pragma unroll
            for (int off = 4; off < 32; off <<= 1) {
                uint32_t u = __shfl_xor_sync(0xffffffffu, *reinterpret_cast<uint32_t*>(&hm), off);
                hm = __hmax2(hm, *reinterpret_cast<__half2*>(&u));
            }
            if (lane < 4) {   // lane == t4
                float2 f = __half22float2(hm);
                colmax[wm * 128 + wn * 64 + nt * 8 + 2 * t4]     = f.x;
                colmax[wm * 128 + wn * 64 + nt * 8 + 2 * t4 + 1] = f.y;
            }
        }
        __syncthreads();

        // ---- cross-warp max over t, then f32 sum over l per query ----
        {
            float v = fmaxf(colmax[tid], colmax[128 + tid]);
            #pragma unroll
            for (int off = 16; off; off >>= 1)
                v += __shfl_xor_sync(0xffffffffu, v, off);
            if (lane == 0)
                out[(qg * 4 + warp) * ND + dbase + dd] = v;
        }

        if (dd == 0) {
            CP_WAIT(0);        // doc1 resident
        }
        __syncthreads();       // colmax reusable / buf1 visible to all
    }
}

// ---------------------------------------------------------------------------
extern "C" void kernel_launch(void* const* d_in, const int* in_sizes, int n_in,
                              void* d_out, int out_size) {
    const float* doc   = (const float*)d_in[0];   // [128,128,128]
    const float* query = (const float*)d_in[1];   // [128,128,32]
    float* out = (float*)d_out;                   // [128,128]

    cudaFuncSetAttribute(maxsim_kernel, cudaFuncAttributeMaxDynamicSharedMemorySize, SMEM_TOTAL);

    conv_all_kernel<<<1152, 256>>>(doc, query);

    dim3 grid(ND / 2, LQ);   // 64 doc-pairs x 32 query groups
    maxsim_kernel<<<grid, 128, SMEM_TOTAL>>>(out);
}

// round 7
// speedup vs baseline: 1.9152x; 1.0786x over previous
#include <cuda_runtime.h>
#include <cuda_fp16.h>
#include <cstdint>

#define ND 128
#define NQ 128
#define LD 128
#define LQ 32
#define EDIM 128

// f16 staging (device globals: no allocation allowed)
__device__ __half g_doc[ND * LD * EDIM];      // [d][t][e]
__device__ __half g_qT[NQ * LQ * EDIM];       // [q][l][e]

// ---------------------------------------------------------------------------
// Merged conversion kernel: blocks [0,1024) convert doc, [1024,1152) convert q
// ---------------------------------------------------------------------------
__global__ void conv_all_kernel(const float* __restrict__ doc, const float* __restrict__ q) {
    __shared__ float s[128 * 33];
    if (blockIdx.x < 1024) {
        int base = blockIdx.x * blockDim.x + threadIdx.x;    // 262144 threads
        #pragma unroll
        for (int it = 0; it < 2; it++) {
            int i = base + it * 262144;
            float4 v = reinterpret_cast<const float4*>(doc)[i];
            __half2 lo = __floats2half2_rn(v.x, v.y);
            __half2 hi = __floats2half2_rn(v.z, v.w);
            uint2 o;
            o.x = *reinterpret_cast<uint32_t*>(&lo);
            o.y = *reinterpret_cast<uint32_t*>(&hi);
            reinterpret_cast<uint2*>(g_doc)[i] = o;
        }
    } else {
        // in[q][e][l] (e:128, l:32)  ->  g_qT[q][l][e]
        int qq = blockIdx.x - 1024;
        const float* src = q + qq * 4096;
        int tid = threadIdx.x;  // 256
        #pragma unroll
        for (int i = 0; i < 16; i++) {
            int idx = tid + i * 256;
            int e = idx >> 5, l = idx & 31;
            s[e * 33 + l] = src[idx];
        }
        __syncthreads();
        __half* dst = g_qT + qq * 4096;
        #pragma unroll
        for (int i = 0; i < 16; i++) {
            int idx = tid + i * 256;
            int l = idx >> 7, e = idx & 127;
            dst[idx] = __float2half_rn(s[e * 33 + l]);
        }
    }
}

// ---------------------------------------------------------------------------
// Primitives
// ---------------------------------------------------------------------------
__device__ __forceinline__ void mma16816_f16(uint32_t* c, const uint32_t* a, const uint32_t* b) {
    asm volatile(
        "mma.sync.aligned.m16n8k16.row.col.f16.f16.f16.f16 "
        "{%0,%1}, {%2,%3,%4,%5}, {%6,%7}, {%0,%1};\n"
        : "+r"(c[0]), "+r"(c[1])
        : "r"(a[0]), "r"(a[1]), "r"(a[2]), "r"(a[3]),
          "r"(b[0]), "r"(b[1]));
}

#define LDSM_X4(r0, r1, r2, r3, addr) \
    asm volatile("ldmatrix.sync.aligned.m8n8.x4.shared.b16 {%0,%1,%2,%3}, [%4];" \
                 : "=r"(r0), "=r"(r1), "=r"(r2), "=r"(r3) : "r"(addr))

__device__ __forceinline__ uint32_t smem_u32(const void* p) {
    uint32_t a;
    asm("{ .reg .u64 t; cvta.to.shared.u64 t, %1; cvt.u32.u64 %0, t; }" : "=r"(a) : "l"(p));
    return a;
}

#define CP16(saddr, gptr) \
    asm volatile("cp.async.cg.shared.global [%0], [%1], 16;" :: "r"(saddr), "l"(gptr))
#define CP_COMMIT() asm volatile("cp.async.commit_group;")
#define CP_WAIT(n)  asm volatile("cp.async.wait_group %0;" :: "n"(n))

// padded smem row: 136 f16 = 272 B (conflict-free LDSM, verified R4/R5)
#define ROWB 272
#define TILE_BYTES (128 * ROWB)                  // 34816
#define A_OFF(dd) ((dd) * TILE_BYTES)
#define B_OFF (2 * TILE_BYTES)
#define CM_OFF (3 * TILE_BYTES)                  // colmax [2][2][128] floats = 2048 B
#define SMEM_TOTAL (3 * TILE_BYTES + 2048)       // 106496

// CTA: 256 threads = 8 warps in 2(doc) x 2(m) x 2(n); warp tile 64x64, f16 acc.
// Both docs computed concurrently by disjoint warp quads.
__global__ void __launch_bounds__(256) maxsim_kernel(float* __restrict__ out) {
    extern __shared__ char smem[];
    float* colmax = reinterpret_cast<float*>(smem + CM_OFF);   // [doc][wm][128]

    const int dbase = blockIdx.x * 2;
    const int qg = blockIdx.y;
    const int tid = threadIdx.x;
    const int warp = tid >> 5;
    const int lane = tid & 31;
    const int wd = warp >> 2;         // doc within pair
    const int wm = (warp >> 1) & 1;   // m half
    const int wn = warp & 1;          // n half
    const int t4 = lane & 3;
    const int matid = lane >> 3;
    const int mrow = lane & 7;

    const uint32_t sbase = smem_u32(smem);

    // ---- async tile loads: q + both docs ----
    {
        const uint4* srcq  = reinterpret_cast<const uint4*>(g_qT + qg * 4 * LQ * EDIM);
        const uint4* srcd0 = reinterpret_cast<const uint4*>(g_doc + dbase * LD * EDIM);
        const uint4* srcd1 = reinterpret_cast<const uint4*>(g_doc + (dbase + 1) * LD * EDIM);
        #pragma unroll
        for (int i = 0; i < 8; i++) {
            int idx = tid + i * 256;                 // 0..2047
            int row = idx >> 4, col = idx & 15;
            uint32_t soff = (uint32_t)(row * 17 + col) * 16;
            CP16(sbase + B_OFF + soff, srcq + idx);
            CP16(sbase + A_OFF(0) + soff, srcd0 + idx);
            CP16(sbase + A_OFF(1) + soff, srcd1 + idx);
        }
        CP_COMMIT();
    }

    // LDSM per-lane offsets (verified R4 mapping)
    uint32_t arow_off[4];
    #pragma unroll
    for (int mt = 0; mt < 4; mt++)
        arow_off[mt] = (uint32_t)((wm * 64 + mt * 16 + (matid & 1) * 8 + mrow) * ROWB
                                  + (matid >> 1) * 16);
    uint32_t brow_off[4];
    #pragma unroll
    for (int np = 0; np < 4; np++)
        brow_off[np] = (uint32_t)(B_OFF + (wn * 64 + np * 16 + (matid >> 1) * 8 + mrow) * ROWB
                                  + (matid & 1) * 16);

    CP_WAIT(0);
    __syncthreads();

    const uint32_t sA = sbase + A_OFF(wd);

    uint32_t acc[4][8][2];
    #pragma unroll
    for (int mt = 0; mt < 4; mt++)
        #pragma unroll
        for (int nt = 0; nt < 8; nt++) {
            acc[mt][nt][0] = 0u;
            acc[mt][nt][1] = 0u;
        }

    #pragma unroll
    for (int k0 = 0; k0 < EDIM; k0 += 16) {
        uint32_t a[4][4], b[8][2];
        #pragma unroll
        for (int mt = 0; mt < 4; mt++)
            LDSM_X4(a[mt][0], a[mt][1], a[mt][2], a[mt][3], sA + arow_off[mt] + k0 * 2);
        #pragma unroll
        for (int np = 0; np < 4; np++) {
            uint32_t t0, t1, t2, t3;
            LDSM_X4(t0, t1, t2, t3, sbase + brow_off[np] + k0 * 2);
            b[2 * np][0] = t0; b[2 * np][1] = t1;
            b[2 * np + 1][0] = t2; b[2 * np + 1][1] = t3;
        }
        #pragma unroll
        for (int mt = 0; mt < 4; mt++)
            #pragma unroll
            for (int nt = 0; nt < 8; nt++)
                mma16816_f16(acc[mt][nt], a[mt], b[nt]);
    }

    // ---- warp max over its 64 doc-token rows (packed f16x2 per col pair) ----
    #pragma unroll
    for (int nt = 0; nt < 8; nt++) {
        __half2 hm = __hmax2(*reinterpret_cast<__half2*>(&acc[0][nt][0]),
                             *reinterpret_cast<__half2*>(&acc[0][nt][1]));
        #pragma unroll
        for (int mt = 1; mt < 4; mt++) {
            hm = __hmax2(hm, *reinterpret_cast<__half2*>(&acc[mt][nt][0]));
            hm = __hmax2(hm, *reinterpret_cast<__half2*>(&acc[mt][nt][1]));
        }
        #pragma unroll
        for (int off = 4; off < 32; off <<= 1) {
            uint32_t u = __shfl_xor_sync(0xffffffffu, *reinterpret_cast<uint32_t*>(&hm), off);
            hm = __hmax2(hm, *reinterpret_cast<__half2*>(&u));
        }
        if (lane < 4) {   // lane == t4
            float2 f = __half22float2(hm);
            colmax[wd * 256 + wm * 128 + wn * 64 + nt * 8 + 2 * t4]     = f.x;
            colmax[wd * 256 + wm * 128 + wn * 64 + nt * 8 + 2 * t4 + 1] = f.y;
        }
    }
    __syncthreads();

    // ---- cross-warp max over t, then f32 sum over l per query ----
    {
        const int col = tid & 127;          // ql index within group; tid>>7 = doc
        const int dd = tid >> 7;
        float v = fmaxf(colmax[dd * 256 + col], colmax[dd * 256 + 128 + col]);
        #pragma unroll
        for (int off = 16; off; off >>= 1)
            v += __shfl_xor_sync(0xffffffffu, v, off);
        if (lane == 0)
            out[(qg * 4 + (col >> 5)) * ND + dbase + dd] = v;
    }
}

// ---------------------------------------------------------------------------
extern "C" void kernel_launch(void* const* d_in, const int* in_sizes, int n_in,
                              void* d_out, int out_size) {
    const float* doc   = (const float*)d_in[0];   // [128,128,128]
    const float* query = (const float*)d_in[1];   // [128,128,32]
    float* out = (float*)d_out;                   // [128,128]

    cudaFuncSetAttribute(maxsim_kernel, cudaFuncAttributeMaxDynamicSharedMemorySize, SMEM_TOTAL);

    conv_all_kernel<<<1152, 256>>>(doc, query);

    dim3 grid(ND / 2, LQ);   // 64 doc-pairs x 32 query groups
    maxsim_kernel<<<grid, 256, SMEM_TOTAL>>>(out);
}